// round 14
// baseline (speedup 1.0000x reference)
#include <cuda_runtime.h>
#include <cuda_fp16.h>
#include <math.h>

#define NN 100000
#define IN_CH 128
#define HID 64
#define OUT_CH 32
#define SLOT_W 64
#define SX_STRIDE 132
#define SA_STRIDE 68

// Scratch (no runtime allocation allowed)
__device__ int    g_cnt[NN];                    // degree counter / cursor
__device__ float  g_dinv[NN];
__device__ int    g_slot[(size_t)NN * SLOT_W];  // fixed-width CSR: src ids
__device__ __half g_t1h[(size_t)NN * HID];      // x@W1 raw (fp16)
__device__ __half g_h1h[(size_t)NN * HID];      // relu(agg1+b1)*dinv[v] (fp16)

// ---------------- f32x2 helpers ----------------
__device__ __forceinline__ unsigned long long pack2(float lo, float hi) {
    unsigned long long r;
    asm("mov.b64 %0, {%1, %2};" : "=l"(r) : "f"(lo), "f"(hi));
    return r;
}
__device__ __forceinline__ void ffma2(unsigned long long& d,
                                      unsigned long long a, unsigned long long b) {
    asm("fma.rn.f32x2 %0, %1, %2, %0;" : "+l"(d) : "l"(a), "l"(b));
}
__device__ __forceinline__ float2 unpack2(unsigned long long v) {
    float2 f;
    asm("mov.b64 {%0, %1}, %2;" : "=f"(f.x), "=f"(f.y) : "l"(v));
    return f;
}

// load 4 halves as two float2
__device__ __forceinline__ void ldh4(const __half* base, float2& a, float2& b) {
    uint2 u = *(const uint2*)base;
    a = __half22float2(*(__half2*)&u.x);
    b = __half22float2(*(__half2*)&u.y);
}

__device__ __forceinline__ float f4_elem(const float4& v, int i) {
    return (i == 0) ? v.x : (i == 1) ? v.y : (i == 2) ? v.z : v.w;
}

// ---------------- scatter into fixed-width slots (4 edges/thread) ----------------
__global__ void k_scatter(const int* __restrict__ src, const int* __restrict__ dst, int E) {
    int t = blockIdx.x * blockDim.x + threadIdx.x;
    int e4 = t << 2;
    if (e4 + 3 < E) {
        int4 s4 = *(const int4*)&src[e4];
        int4 d4 = *(const int4*)&dst[e4];
        int p;
        p = atomicAdd(&g_cnt[d4.x], 1); if (p < SLOT_W) g_slot[d4.x * SLOT_W + p] = s4.x;
        p = atomicAdd(&g_cnt[d4.y], 1); if (p < SLOT_W) g_slot[d4.y * SLOT_W + p] = s4.y;
        p = atomicAdd(&g_cnt[d4.z], 1); if (p < SLOT_W) g_slot[d4.z * SLOT_W + p] = s4.z;
        p = atomicAdd(&g_cnt[d4.w], 1); if (p < SLOT_W) g_slot[d4.w * SLOT_W + p] = s4.w;
    } else {
        for (int e = e4; e < E; e++) {
            int s = src[e], d = dst[e];
            int p = atomicAdd(&g_cnt[d], 1);
            if (p < SLOT_W) g_slot[d * SLOT_W + p] = s;
        }
    }
}

__global__ void k_dinv() {
    int i = blockIdx.x * blockDim.x + threadIdx.x;
    if (i < NN) g_dinv[i] = rsqrtf((float)(g_cnt[i] + 1));  // +1 self loop
}

// ---------------- GEMM1: t1h = half(x @ W1)  (raw; 128x64 tile, 4x8/thread) ----------------
__global__ void __launch_bounds__(256) k_gemm1(const float* __restrict__ x,
                                               const float* __restrict__ W1) {
    extern __shared__ float smem[];
    float* sW = smem;                     // 128*64 = 32 KB
    float* sX = smem + IN_CH * HID;       // 128*132 = 67.6 KB
    int tid = threadIdx.x;
    for (int i = tid; i < (IN_CH * HID) / 4; i += 256)
        ((float4*)sW)[i] = ((const float4*)W1)[i];
    int base = blockIdx.x * 128;
    for (int i = tid; i < 128 * 32; i += 256) {
        int row = i >> 5, k4 = (i & 31) << 2;
        int gr = base + row;
        float4 v = make_float4(0.f, 0.f, 0.f, 0.f);
        if (gr < NN) v = *(const float4*)&x[(size_t)gr * IN_CH + k4];
        *(float4*)&sX[row * SX_STRIDE + k4] = v;
    }
    __syncthreads();

    int r0 = (tid >> 3) * 4, c0 = (tid & 7) * 8;
    unsigned long long acc[4][4];
#pragma unroll
    for (int r = 0; r < 4; r++)
#pragma unroll
        for (int c = 0; c < 4; c++) acc[r][c] = 0ULL;

    const float* xr = &sX[r0 * SX_STRIDE];
#pragma unroll 2
    for (int k0 = 0; k0 < IN_CH; k0 += 4) {
        float4 xv0 = *(const float4*)&xr[k0];
        float4 xv1 = *(const float4*)&xr[k0 + SX_STRIDE];
        float4 xv2 = *(const float4*)&xr[k0 + 2 * SX_STRIDE];
        float4 xv3 = *(const float4*)&xr[k0 + 3 * SX_STRIDE];
#pragma unroll
        for (int kk = 0; kk < 4; kk++) {
            int k = k0 + kk;
            float x0 = f4_elem(xv0, kk);
            float x1 = f4_elem(xv1, kk);
            float x2 = f4_elem(xv2, kk);
            float x3 = f4_elem(xv3, kk);
            unsigned long long X0 = pack2(x0, x0);
            unsigned long long X1 = pack2(x1, x1);
            unsigned long long X2 = pack2(x2, x2);
            unsigned long long X3 = pack2(x3, x3);
            ulonglong2 wa = *(const ulonglong2*)&sW[k * HID + c0];
            ulonglong2 wb = *(const ulonglong2*)&sW[k * HID + c0 + 4];
            ffma2(acc[0][0], X0, wa.x); ffma2(acc[0][1], X0, wa.y);
            ffma2(acc[0][2], X0, wb.x); ffma2(acc[0][3], X0, wb.y);
            ffma2(acc[1][0], X1, wa.x); ffma2(acc[1][1], X1, wa.y);
            ffma2(acc[1][2], X1, wb.x); ffma2(acc[1][3], X1, wb.y);
            ffma2(acc[2][0], X2, wa.x); ffma2(acc[2][1], X2, wa.y);
            ffma2(acc[2][2], X2, wb.x); ffma2(acc[2][3], X2, wb.y);
            ffma2(acc[3][0], X3, wa.x); ffma2(acc[3][1], X3, wa.y);
            ffma2(acc[3][2], X3, wb.x); ffma2(acc[3][3], X3, wb.y);
        }
    }
#pragma unroll
    for (int rr = 0; rr < 4; rr++) {
        int gr = base + r0 + rr;
        if (gr < NN) {
            float2 f0 = unpack2(acc[rr][0]), f1 = unpack2(acc[rr][1]);
            float2 f2 = unpack2(acc[rr][2]), f3 = unpack2(acc[rr][3]);
            uint4 h;
            *(__half2*)&h.x = __floats2half2_rn(f0.x, f0.y);
            *(__half2*)&h.y = __floats2half2_rn(f1.x, f1.y);
            *(__half2*)&h.z = __floats2half2_rn(f2.x, f2.y);
            *(__half2*)&h.w = __floats2half2_rn(f3.x, f3.y);
            *(uint4*)&g_t1h[gr * HID + c0] = h;
        }
    }
}

// ---------------- agg1: weighted pull over raw t1h; fold dinv[v] into output ----------------
// h1h[v] = relu(dinv[v]*(sum_s t1[s]*dinv[s] + t1[v]*dinv[v]) + b1) * dinv[v]
__global__ void __launch_bounds__(256) k_agg1(const float* __restrict__ b1) {
    int v = blockIdx.x * 16 + (threadIdx.x >> 4);
    int c = (threadIdx.x & 15) << 2;
    float dv = g_dinv[v];
    float2 s0, s1;
    ldh4(&g_t1h[v * HID + c], s0, s1);
    float4 acc = make_float4(s0.x * dv, s0.y * dv, s1.x * dv, s1.y * dv);
    int deg = g_cnt[v];
    if (deg > SLOT_W) deg = SLOT_W;
    const int* sp = &g_slot[v * SLOT_W];
    int j = 0;
    for (; j + 4 <= deg; j += 4) {
        int4 nn = *(const int4*)&sp[j];
        float w0 = g_dinv[nn.x], w1 = g_dinv[nn.y];
        float w2 = g_dinv[nn.z], w3 = g_dinv[nn.w];
        float2 a0, a1, b0, b1v, c0v, c1, d0, d1;
        ldh4(&g_t1h[nn.x * HID + c], a0, a1);
        ldh4(&g_t1h[nn.y * HID + c], b0, b1v);
        ldh4(&g_t1h[nn.z * HID + c], c0v, c1);
        ldh4(&g_t1h[nn.w * HID + c], d0, d1);
        acc.x += a0.x * w0 + b0.x * w1 + c0v.x * w2 + d0.x * w3;
        acc.y += a0.y * w0 + b0.y * w1 + c0v.y * w2 + d0.y * w3;
        acc.z += a1.x * w0 + b1v.x * w1 + c1.x * w2 + d1.x * w3;
        acc.w += a1.y * w0 + b1v.y * w1 + c1.y * w2 + d1.y * w3;
    }
    for (; j < deg; j++) {
        int n0 = sp[j];
        float w0 = g_dinv[n0];
        float2 a0, a1;
        ldh4(&g_t1h[n0 * HID + c], a0, a1);
        acc.x += a0.x * w0; acc.y += a0.y * w0;
        acc.z += a1.x * w0; acc.w += a1.y * w0;
    }
    float4 bb = *(const float4*)&b1[c];
    acc.x = fmaxf(fmaf(acc.x, dv, bb.x), 0.f) * dv;
    acc.y = fmaxf(fmaf(acc.y, dv, bb.y), 0.f) * dv;
    acc.z = fmaxf(fmaf(acc.z, dv, bb.z), 0.f) * dv;
    acc.w = fmaxf(fmaf(acc.w, dv, bb.w), 0.f) * dv;
    uint2 h;
    *(__half2*)&h.x = __floats2half2_rn(acc.x, acc.y);
    *(__half2*)&h.y = __floats2half2_rn(acc.z, acc.w);
    *(uint2*)&g_h1h[v * HID + c] = h;
}

// ---------------- fused agg2 + heads: 512 threads, 32 nodes/block ----------------
// Phase 1: agg[v] = dinv[v]*(sum_s h1h[s] + h1h[v]) -> smem (fp32)
// Phase 2 (256 threads): mu/ls = agg @ {Wmu,Wls} + {bmu,bls} (packed f32x2)
__global__ void __launch_bounds__(512) k_agg2out(const float* __restrict__ Wmu,
                                                 const float* __restrict__ bmu,
                                                 const float* __restrict__ Wls,
                                                 const float* __restrict__ bls,
                                                 float* __restrict__ out) {
    __shared__ unsigned long long sW2[HID * OUT_CH];  // 16 KB interleaved (mu, ls)
    __shared__ float sA[32 * SA_STRIDE];              // 8.7 KB
    int tid = threadIdx.x;
    for (int i = tid; i < HID * OUT_CH; i += 512) sW2[i] = pack2(Wmu[i], Wls[i]);

    int base = blockIdx.x * 32;
    {
        int vl = tid >> 4;              // 0..31 local node
        int v = base + vl;
        int c = (tid & 15) << 2;        // half index
        float2 s0, s1;
        ldh4(&g_h1h[v * HID + c], s0, s1);
        float4 acc = make_float4(s0.x, s0.y, s1.x, s1.y);
        int deg = g_cnt[v];
        if (deg > SLOT_W) deg = SLOT_W;
        const int* sp = &g_slot[v * SLOT_W];
        int j = 0;
        for (; j + 4 <= deg; j += 4) {
            int4 nn = *(const int4*)&sp[j];
            float2 a0, a1, b0, b1v, c0v, c1, d0, d1;
            ldh4(&g_h1h[nn.x * HID + c], a0, a1);
            ldh4(&g_h1h[nn.y * HID + c], b0, b1v);
            ldh4(&g_h1h[nn.z * HID + c], c0v, c1);
            ldh4(&g_h1h[nn.w * HID + c], d0, d1);
            acc.x += (a0.x + b0.x) + (c0v.x + d0.x);
            acc.y += (a0.y + b0.y) + (c0v.y + d0.y);
            acc.z += (a1.x + b1v.x) + (c1.x + d1.x);
            acc.w += (a1.y + b1v.y) + (c1.y + d1.y);
        }
        for (; j < deg; j++) {
            int n0 = sp[j];
            float2 a0, a1;
            ldh4(&g_h1h[n0 * HID + c], a0, a1);
            acc.x += a0.x; acc.y += a0.y;
            acc.z += a1.x; acc.w += a1.y;
        }
        float dv = g_dinv[v];
        *(float4*)&sA[vl * SA_STRIDE + c] =
            make_float4(acc.x * dv, acc.y * dv, acc.z * dv, acc.w * dv);
    }
    __syncthreads();

    if (tid < 256) {
        int row = tid >> 3;   // 0..31
        int cg = tid & 7;
        unsigned long long acc[4];
#pragma unroll
        for (int c = 0; c < 4; c++) acc[c] = pack2(bmu[cg + 8 * c], bls[cg + 8 * c]);

        const float* ar = &sA[row * SA_STRIDE];
#pragma unroll 8
        for (int k = 0; k < HID; k++) {
            float a = ar[k];
            unsigned long long a2 = pack2(a, a);
            const unsigned long long* wr = &sW2[k * OUT_CH + cg];
            ffma2(acc[0], a2, wr[0]);
            ffma2(acc[1], a2, wr[8]);
            ffma2(acc[2], a2, wr[16]);
            ffma2(acc[3], a2, wr[24]);
        }
        int v = base + row;
#pragma unroll
        for (int c = 0; c < 4; c++) {
            float2 r = unpack2(acc[c]);
            out[(size_t)v * OUT_CH + cg + 8 * c] = r.x;
            out[(size_t)NN * OUT_CH + (size_t)v * OUT_CH + cg + 8 * c] = r.y;
        }
    }
}

extern "C" void kernel_launch(void* const* d_in, const int* in_sizes, int n_in,
                              void* d_out, int out_size) {
    const float* x   = (const float*)d_in[0];
    const int*   ei  = (const int*)d_in[1];
    const float* W1  = (const float*)d_in[2];
    const float* b1  = (const float*)d_in[3];
    const float* Wmu = (const float*)d_in[4];
    const float* bmu = (const float*)d_in[5];
    const float* Wls = (const float*)d_in[6];
    const float* bls = (const float*)d_in[7];
    float* out = (float*)d_out;

    int E = in_sizes[1] / 2;
    const int* src = ei;
    const int* dst = ei + E;

    static cudaStream_t s_side = nullptr;
    static cudaEvent_t ev_root = nullptr, ev_gemm = nullptr;
    if (!s_side) {
        cudaStreamCreateWithFlags(&s_side, cudaStreamNonBlocking);
        cudaEventCreateWithFlags(&ev_root, cudaEventDisableTiming);
        cudaEventCreateWithFlags(&ev_gemm, cudaEventDisableTiming);
    }

    int gemm_smem = (IN_CH * HID + 128 * SX_STRIDE) * sizeof(float);  // 100352
    cudaFuncSetAttribute(k_gemm1, cudaFuncAttributeMaxDynamicSharedMemorySize, gemm_smem);

    void* p_cnt = nullptr;
    cudaGetSymbolAddress(&p_cnt, g_cnt);

    // fork: gemm1 (independent of graph preprocessing) on side stream
    cudaEventRecord(ev_root, 0);
    cudaStreamWaitEvent(s_side, ev_root, 0);
    k_gemm1<<<(NN + 127) / 128, 256, gemm_smem, s_side>>>(x, W1);
    cudaEventRecord(ev_gemm, s_side);

    // main stream: graph preprocessing
    cudaMemsetAsync(p_cnt, 0, NN * sizeof(int));
    int escat = (E + 3) / 4;
    k_scatter<<<(escat + 255) / 256, 256>>>(src, dst, E);
    k_dinv<<<(NN + 255) / 256, 256>>>();

    // join, then aggregation + fused heads
    cudaStreamWaitEvent(0, ev_gemm, 0);
    k_agg1<<<NN / 16, 256>>>(b1);
    k_agg2out<<<(NN + 31) / 32, 512>>>(Wmu, bmu, Wls, bls, out);
}

// round 15
// speedup vs baseline: 1.4975x; 1.4975x over previous
#include <cuda_runtime.h>
#include <cuda_fp16.h>
#include <math.h>

#define NN 100000
#define IN_CH 128
#define HID 64
#define OUT_CH 32
#define SLOT_W 64
#define SX_STRIDE 132
#define SA_STRIDE 68

// Scratch (no runtime allocation allowed)
__device__ int    g_cnt[NN];                    // degree counter / cursor
__device__ float  g_dinv[NN];
__device__ int    g_slot[(size_t)NN * SLOT_W];  // fixed-width CSR: src ids
__device__ __half g_t1h[(size_t)NN * HID];      // x@W1 raw (fp16)
__device__ __half g_h1h[(size_t)NN * HID];      // relu(agg1+b1)*dinv[v] (fp16)

// ---------------- f32x2 helpers ----------------
__device__ __forceinline__ unsigned long long pack2(float lo, float hi) {
    unsigned long long r;
    asm("mov.b64 %0, {%1, %2};" : "=l"(r) : "f"(lo), "f"(hi));
    return r;
}
__device__ __forceinline__ void ffma2(unsigned long long& d,
                                      unsigned long long a, unsigned long long b) {
    asm("fma.rn.f32x2 %0, %1, %2, %0;" : "+l"(d) : "l"(a), "l"(b));
}
__device__ __forceinline__ float2 unpack2(unsigned long long v) {
    float2 f;
    asm("mov.b64 {%0, %1}, %2;" : "=f"(f.x), "=f"(f.y) : "l"(v));
    return f;
}

// load 4 halves as two float2
__device__ __forceinline__ void ldh4(const __half* base, float2& a, float2& b) {
    uint2 u = *(const uint2*)base;
    a = __half22float2(*(__half2*)&u.x);
    b = __half22float2(*(__half2*)&u.y);
}

// ---------------- scatter into fixed-width slots (4 edges/thread) ----------------
__global__ void k_scatter(const int* __restrict__ src, const int* __restrict__ dst, int E) {
    int t = blockIdx.x * blockDim.x + threadIdx.x;
    int e4 = t << 2;
    if (e4 + 3 < E) {
        int4 s4 = *(const int4*)&src[e4];
        int4 d4 = *(const int4*)&dst[e4];
        int p;
        p = atomicAdd(&g_cnt[d4.x], 1); if (p < SLOT_W) g_slot[d4.x * SLOT_W + p] = s4.x;
        p = atomicAdd(&g_cnt[d4.y], 1); if (p < SLOT_W) g_slot[d4.y * SLOT_W + p] = s4.y;
        p = atomicAdd(&g_cnt[d4.z], 1); if (p < SLOT_W) g_slot[d4.z * SLOT_W + p] = s4.z;
        p = atomicAdd(&g_cnt[d4.w], 1); if (p < SLOT_W) g_slot[d4.w * SLOT_W + p] = s4.w;
    } else {
        for (int e = e4; e < E; e++) {
            int s = src[e], d = dst[e];
            int p = atomicAdd(&g_cnt[d], 1);
            if (p < SLOT_W) g_slot[d * SLOT_W + p] = s;
        }
    }
}

__global__ void k_dinv() {
    int i = blockIdx.x * blockDim.x + threadIdx.x;
    if (i < NN) g_dinv[i] = rsqrtf((float)(g_cnt[i] + 1));  // +1 self loop
}

// ---------------- GEMM1: t1h = half(x @ W1)  (raw; 128x64 tile, 4x8/thread) ----------------
__global__ void __launch_bounds__(256) k_gemm1(const float* __restrict__ x,
                                               const float* __restrict__ W1) {
    extern __shared__ float smem[];
    float* sW = smem;                     // 128*64 = 32 KB
    float* sX = smem + IN_CH * HID;       // 128*132 = 67.6 KB
    int tid = threadIdx.x;
    for (int i = tid; i < (IN_CH * HID) / 4; i += 256)
        ((float4*)sW)[i] = ((const float4*)W1)[i];
    int base = blockIdx.x * 128;
    for (int i = tid; i < 128 * 32; i += 256) {
        int row = i >> 5, k4 = (i & 31) << 2;
        int gr = base + row;
        float4 v = make_float4(0.f, 0.f, 0.f, 0.f);
        if (gr < NN) v = *(const float4*)&x[(size_t)gr * IN_CH + k4];
        *(float4*)&sX[row * SX_STRIDE + k4] = v;
    }
    __syncthreads();

    int r0 = (tid >> 3) * 4, c0 = (tid & 7) * 8;
    unsigned long long acc[4][4];
#pragma unroll
    for (int r = 0; r < 4; r++)
#pragma unroll
        for (int c = 0; c < 4; c++) acc[r][c] = 0ULL;

    const float* xr = &sX[r0 * SX_STRIDE];
#pragma unroll 4
    for (int k = 0; k < IN_CH; k++) {
        float x0 = xr[k];
        float x1 = xr[k + SX_STRIDE];
        float x2 = xr[k + 2 * SX_STRIDE];
        float x3 = xr[k + 3 * SX_STRIDE];
        unsigned long long X0 = pack2(x0, x0);
        unsigned long long X1 = pack2(x1, x1);
        unsigned long long X2 = pack2(x2, x2);
        unsigned long long X3 = pack2(x3, x3);
        ulonglong2 wa = *(const ulonglong2*)&sW[k * HID + c0];
        ulonglong2 wb = *(const ulonglong2*)&sW[k * HID + c0 + 4];
        ffma2(acc[0][0], X0, wa.x); ffma2(acc[0][1], X0, wa.y);
        ffma2(acc[0][2], X0, wb.x); ffma2(acc[0][3], X0, wb.y);
        ffma2(acc[1][0], X1, wa.x); ffma2(acc[1][1], X1, wa.y);
        ffma2(acc[1][2], X1, wb.x); ffma2(acc[1][3], X1, wb.y);
        ffma2(acc[2][0], X2, wa.x); ffma2(acc[2][1], X2, wa.y);
        ffma2(acc[2][2], X2, wb.x); ffma2(acc[2][3], X2, wb.y);
        ffma2(acc[3][0], X3, wa.x); ffma2(acc[3][1], X3, wa.y);
        ffma2(acc[3][2], X3, wb.x); ffma2(acc[3][3], X3, wb.y);
    }
#pragma unroll
    for (int rr = 0; rr < 4; rr++) {
        int gr = base + r0 + rr;
        if (gr < NN) {
            float2 f0 = unpack2(acc[rr][0]), f1 = unpack2(acc[rr][1]);
            float2 f2 = unpack2(acc[rr][2]), f3 = unpack2(acc[rr][3]);
            uint4 h;
            *(__half2*)&h.x = __floats2half2_rn(f0.x, f0.y);
            *(__half2*)&h.y = __floats2half2_rn(f1.x, f1.y);
            *(__half2*)&h.z = __floats2half2_rn(f2.x, f2.y);
            *(__half2*)&h.w = __floats2half2_rn(f3.x, f3.y);
            *(uint4*)&g_t1h[gr * HID + c0] = h;
        }
    }
}

// ---------------- agg1: weighted pull over raw t1h; fold dinv[v] into output ----------------
// h1h[v] = relu(dinv[v]*(sum_s t1[s]*dinv[s] + t1[v]*dinv[v]) + b1) * dinv[v]
__global__ void __launch_bounds__(256) k_agg1(const float* __restrict__ b1) {
    int v = blockIdx.x * 16 + (threadIdx.x >> 4);
    int c = (threadIdx.x & 15) << 2;
    float dv = g_dinv[v];
    float2 s0, s1;
    ldh4(&g_t1h[v * HID + c], s0, s1);
    float4 acc = make_float4(s0.x * dv, s0.y * dv, s1.x * dv, s1.y * dv);
    int deg = g_cnt[v];
    if (deg > SLOT_W) deg = SLOT_W;
    const int* sp = &g_slot[v * SLOT_W];
    int j = 0;
    for (; j + 4 <= deg; j += 4) {
        int4 nn = *(const int4*)&sp[j];
        float w0 = g_dinv[nn.x], w1 = g_dinv[nn.y];
        float w2 = g_dinv[nn.z], w3 = g_dinv[nn.w];
        float2 a0, a1, b0, b1v, c0v, c1, d0, d1;
        ldh4(&g_t1h[nn.x * HID + c], a0, a1);
        ldh4(&g_t1h[nn.y * HID + c], b0, b1v);
        ldh4(&g_t1h[nn.z * HID + c], c0v, c1);
        ldh4(&g_t1h[nn.w * HID + c], d0, d1);
        acc.x += a0.x * w0 + b0.x * w1 + c0v.x * w2 + d0.x * w3;
        acc.y += a0.y * w0 + b0.y * w1 + c0v.y * w2 + d0.y * w3;
        acc.z += a1.x * w0 + b1v.x * w1 + c1.x * w2 + d1.x * w3;
        acc.w += a1.y * w0 + b1v.y * w1 + c1.y * w2 + d1.y * w3;
    }
    for (; j < deg; j++) {
        int n0 = sp[j];
        float w0 = g_dinv[n0];
        float2 a0, a1;
        ldh4(&g_t1h[n0 * HID + c], a0, a1);
        acc.x += a0.x * w0; acc.y += a0.y * w0;
        acc.z += a1.x * w0; acc.w += a1.y * w0;
    }
    float4 bb = *(const float4*)&b1[c];
    acc.x = fmaxf(fmaf(acc.x, dv, bb.x), 0.f) * dv;
    acc.y = fmaxf(fmaf(acc.y, dv, bb.y), 0.f) * dv;
    acc.z = fmaxf(fmaf(acc.z, dv, bb.z), 0.f) * dv;
    acc.w = fmaxf(fmaf(acc.w, dv, bb.w), 0.f) * dv;
    uint2 h;
    *(__half2*)&h.x = __floats2half2_rn(acc.x, acc.y);
    *(__half2*)&h.y = __floats2half2_rn(acc.z, acc.w);
    *(uint2*)&g_h1h[v * HID + c] = h;
}

// ---------------- fused agg2 + heads: 512 threads, 32 nodes/block ----------------
// Phase 1: agg[v] = dinv[v]*(sum_s h1h[s] + h1h[v]) -> smem (fp32)
// Phase 2 (256 threads): mu/ls = agg @ {Wmu,Wls} + {bmu,bls} (packed f32x2)
__global__ void __launch_bounds__(512) k_agg2out(const float* __restrict__ Wmu,
                                                 const float* __restrict__ bmu,
                                                 const float* __restrict__ Wls,
                                                 const float* __restrict__ bls,
                                                 float* __restrict__ out) {
    __shared__ unsigned long long sW2[HID * OUT_CH];  // 16 KB interleaved (mu, ls)
    __shared__ float sA[32 * SA_STRIDE];              // 8.7 KB
    int tid = threadIdx.x;
    for (int i = tid; i < HID * OUT_CH; i += 512) sW2[i] = pack2(Wmu[i], Wls[i]);

    int base = blockIdx.x * 32;
    {
        int vl = tid >> 4;              // 0..31 local node
        int v = base + vl;
        int c = (tid & 15) << 2;        // half index
        float2 s0, s1;
        ldh4(&g_h1h[v * HID + c], s0, s1);
        float4 acc = make_float4(s0.x, s0.y, s1.x, s1.y);
        int deg = g_cnt[v];
        if (deg > SLOT_W) deg = SLOT_W;
        const int* sp = &g_slot[v * SLOT_W];
        int j = 0;
        for (; j + 4 <= deg; j += 4) {
            int4 nn = *(const int4*)&sp[j];
            float2 a0, a1, b0, b1v, c0v, c1, d0, d1;
            ldh4(&g_h1h[nn.x * HID + c], a0, a1);
            ldh4(&g_h1h[nn.y * HID + c], b0, b1v);
            ldh4(&g_h1h[nn.z * HID + c], c0v, c1);
            ldh4(&g_h1h[nn.w * HID + c], d0, d1);
            acc.x += (a0.x + b0.x) + (c0v.x + d0.x);
            acc.y += (a0.y + b0.y) + (c0v.y + d0.y);
            acc.z += (a1.x + b1v.x) + (c1.x + d1.x);
            acc.w += (a1.y + b1v.y) + (c1.y + d1.y);
        }
        for (; j < deg; j++) {
            int n0 = sp[j];
            float2 a0, a1;
            ldh4(&g_h1h[n0 * HID + c], a0, a1);
            acc.x += a0.x; acc.y += a0.y;
            acc.z += a1.x; acc.w += a1.y;
        }
        float dv = g_dinv[v];
        *(float4*)&sA[vl * SA_STRIDE + c] =
            make_float4(acc.x * dv, acc.y * dv, acc.z * dv, acc.w * dv);
    }
    __syncthreads();

    if (tid < 256) {
        int row = tid >> 3;   // 0..31
        int cg = tid & 7;
        unsigned long long acc[4];
#pragma unroll
        for (int c = 0; c < 4; c++) acc[c] = pack2(bmu[cg + 8 * c], bls[cg + 8 * c]);

        const float* ar = &sA[row * SA_STRIDE];
#pragma unroll 8
        for (int k = 0; k < HID; k++) {
            float a = ar[k];
            unsigned long long a2 = pack2(a, a);
            const unsigned long long* wr = &sW2[k * OUT_CH + cg];
            ffma2(acc[0], a2, wr[0]);
            ffma2(acc[1], a2, wr[8]);
            ffma2(acc[2], a2, wr[16]);
            ffma2(acc[3], a2, wr[24]);
        }
        int v = base + row;
#pragma unroll
        for (int c = 0; c < 4; c++) {
            float2 r = unpack2(acc[c]);
            out[(size_t)v * OUT_CH + cg + 8 * c] = r.x;
            out[(size_t)NN * OUT_CH + (size_t)v * OUT_CH + cg + 8 * c] = r.y;
        }
    }
}

extern "C" void kernel_launch(void* const* d_in, const int* in_sizes, int n_in,
                              void* d_out, int out_size) {
    const float* x   = (const float*)d_in[0];
    const int*   ei  = (const int*)d_in[1];
    const float* W1  = (const float*)d_in[2];
    const float* b1  = (const float*)d_in[3];
    const float* Wmu = (const float*)d_in[4];
    const float* bmu = (const float*)d_in[5];
    const float* Wls = (const float*)d_in[6];
    const float* bls = (const float*)d_in[7];
    float* out = (float*)d_out;

    int E = in_sizes[1] / 2;
    const int* src = ei;
    const int* dst = ei + E;

    static cudaStream_t s_side = nullptr;
    static cudaEvent_t ev_root = nullptr, ev_gemm = nullptr;
    if (!s_side) {
        cudaStreamCreateWithFlags(&s_side, cudaStreamNonBlocking);
        cudaEventCreateWithFlags(&ev_root, cudaEventDisableTiming);
        cudaEventCreateWithFlags(&ev_gemm, cudaEventDisableTiming);
    }

    int gemm_smem = (IN_CH * HID + 128 * SX_STRIDE) * sizeof(float);  // 100352
    cudaFuncSetAttribute(k_gemm1, cudaFuncAttributeMaxDynamicSharedMemorySize, gemm_smem);

    void* p_cnt = nullptr;
    cudaGetSymbolAddress(&p_cnt, g_cnt);

    // fork: gemm1 (independent of graph preprocessing) on side stream
    cudaEventRecord(ev_root, 0);
    cudaStreamWaitEvent(s_side, ev_root, 0);
    k_gemm1<<<(NN + 127) / 128, 256, gemm_smem, s_side>>>(x, W1);
    cudaEventRecord(ev_gemm, s_side);

    // main stream: graph preprocessing
    cudaMemsetAsync(p_cnt, 0, NN * sizeof(int));
    int escat = (E + 3) / 4;
    k_scatter<<<(escat + 255) / 256, 256>>>(src, dst, E);
    k_dinv<<<(NN + 255) / 256, 256>>>();

    // join, then aggregation + fused heads
    cudaStreamWaitEvent(0, ev_gemm, 0);
    k_agg1<<<NN / 16, 256>>>(b1);
    k_agg2out<<<(NN + 31) / 32, 512>>>(Wmu, bmu, Wls, bls, out);
}